// round 7
// baseline (speedup 1.0000x reference)
#include <cuda_runtime.h>
#include <cuda_bf16.h>
#include <cstdint>

// Problem constants (H=W=256, SMALL=8, LARGE=16, B=2)
#define HW      65536
#define NB      2
#define WNUM    1024
#define S2      64
#define L2      256
#define NTILE   (WNUM*NB)     // 2048
#define NBLK    1024          // single wave at occ 7 (148*7 = 1036)
// bulk: 1024 blocks * 256 threads * 32 float4 = 8388608 = all of P

__device__ int   g_partner[NB * HW];   // 512 KB (L2-resident)
__device__ float g_corrR[NTILE];       // per-tile nll_sum/c_num
__device__ float g_bulk[NBLK];         // per-block partials (incl. absd corr)
__device__ int   g_sync1;              // scatter barrier (zero-init, rearmed)
__device__ int   g_ticket;             // completion ticket (zero-init, rearmed)

__device__ __forceinline__ float warp_sum(float v) {
    #pragma unroll
    for (int o = 16; o > 0; o >>= 1) v += __shfl_down_sync(0xFFFFFFFFu, v, o);
    return v;
}

// ---------------------------------------------------------------------------
// Single fused kernel; every block does the SAME work (no imbalance tail):
//   scatter 128 entries -> 16 bulk iters -> barrier (long drained) ->
//   corr for 2 tiles (4 warps per tile) -> 16 bulk iters -> reduce/ticket
// ---------------------------------------------------------------------------
__global__ __launch_bounds__(256, 7)
void k_all(const float4* __restrict__ P4,
           const float*  __restrict__ Pf,
           const int*    __restrict__ index_r,
           const int*    __restrict__ lw_abs,
           float*        __restrict__ out) {
    const int bid  = blockIdx.x;
    const int tid  = threadIdx.x;
    const int lane = tid & 31;
    const int wrp  = tid >> 5;

    // ---- phase 0: scatter slice (128 entries per block, coalesced reads) ----
    if (tid < 128) {
        int e    = bid * 128 + tid;            // 0..131071 covers NB*HW
        int b    = e >> 16;
        int j    = e & (HW - 1);
        int idx0 = index_r[(b * 2 + 0) * HW + j];
        int idx1 = index_r[(b * 2 + 1) * HW + j];
        g_partner[b * HW + idx1] = idx0;
    }
    __threadfence();
    __syncthreads();
    if (tid == 0) atomicAdd(&g_sync1, 1);      // arrive now, wait mid-stream

    // ---- phase 1: first half of bulk stream ----
    const int base = bid * 256 + tid;
    float a0 = 0.f, a1 = 0.f;
    #pragma unroll 4
    for (int k = 0; k < 16; k++) {
        float4 p = __ldcs(P4 + base + k * (NBLK * 256));
        a0 += p.x + p.y;
        a1 += p.z + p.w;
    }

    // ---- phase 2: global barrier (all blocks resident; long since drained) ----
    if (tid == 0) {
        while (*((volatile int*)&g_sync1) < NBLK) { }
    }
    __syncthreads();
    __threadfence();

    // ---- phase 3: corr for 2 tiles/block; 4 warps per tile, 64 cols/warp ----
    {
        const int tile = bid * 2 + (wrp >> 2);       // tile = w*2 + b
        const int g    = wrp & 3;                    // warp-in-group
        const int w    = tile >> 1;
        const int b    = tile & 1;
        const int r0   = (w >> 5) << 3;
        const int c0   = (w & 31) << 3;
        const float* Pt = Pf + (size_t)tile * (S2 * L2);

        float nll = 0.f;
        int   cnt = 0;
        #pragma unroll
        for (int h = 0; h < 2; h++) {
            int l  = g * 64 + h * 32 + lane;         // this group's 64 columns
            int lw = __ldg(lw_abs + w * L2 + l);
            int v  = g_partner[b * HW + lw];         // plw
            int i  = (v >> 8) - r0;
            int j  = (v & 255) - c0;
            if ((unsigned)i < 8u && (unsigned)j < 8u && !(v == 0 && lw == 0)) {
                float p = __ldg(Pt + (i * 8 + j) * L2 + l);
                a0  += 1.f - 2.f * p;                // absd corr -> bulk acc
                nll -= __logf(fminf(fmaxf(p, 1e-6f), 1.f - 1e-6f));
                cnt++;
            }
        }
        nll = warp_sum(nll);
        float cf = warp_sum((float)cnt);

        __shared__ float s_nll[8], s_cnt[8];
        if (lane == 0) { s_nll[wrp] = nll; s_cnt[wrp] = cf; }
        __syncthreads();
        if (tid == 0) {
            float n = s_nll[0] + s_nll[1] + s_nll[2] + s_nll[3];
            float c = s_cnt[0] + s_cnt[1] + s_cnt[2] + s_cnt[3];
            g_corrR[bid * 2 + 0] = n / c;
        } else if (tid == 128) {
            float n = s_nll[4] + s_nll[5] + s_nll[6] + s_nll[7];
            float c = s_cnt[4] + s_cnt[5] + s_cnt[6] + s_cnt[7];
            g_corrR[bid * 2 + 1] = n / c;
        }
    }

    // ---- phase 4: second half of bulk stream ----
    #pragma unroll 4
    for (int k = 16; k < 32; k++) {
        float4 p = __ldcs(P4 + base + k * (NBLK * 256));
        a0 += p.x + p.y;
        a1 += p.z + p.w;
    }
    float acc = a0 + a1;

    // ---- block reduction -> g_bulk, ticket ----
    acc = warp_sum(acc);
    __shared__ float red[8];
    __shared__ bool  s_last;
    if (lane == 0) red[wrp] = acc;
    __syncthreads();
    if (wrp == 0) {
        float a = (lane < 8) ? red[lane] : 0.f;
        #pragma unroll
        for (int o = 4; o > 0; o >>= 1) a += __shfl_down_sync(0xFFFFFFFFu, a, o);
        if (lane == 0) {
            g_bulk[bid] = a;
            __threadfence();
            int t = atomicAdd(&g_ticket, 1);
            s_last = (t == NBLK - 1);
        }
    }
    __syncthreads();

    // ---- final fixed-order combine (deterministic) ----
    if (s_last) {
        float sumP = 0.f, sumR = 0.f;
        #pragma unroll
        for (int i = tid; i < NBLK; i += 256) sumP += g_bulk[i];
        #pragma unroll
        for (int i = tid; i < NTILE; i += 256) sumR += g_corrR[i];
        sumP = warp_sum(sumP);
        sumR = warp_sum(sumR);
        __shared__ float sp[8], sr[8];
        if (lane == 0) { sp[wrp] = sumP; sr[wrp] = sumR; }
        __syncthreads();
        if (wrp == 0) {
            float p = (lane < 8) ? sp[lane] : 0.f;
            float r = (lane < 8) ? sr[lane] : 0.f;
            #pragma unroll
            for (int o = 4; o > 0; o >>= 1) {
                p += __shfl_down_sync(0xFFFFFFFFu, p, o);
                r += __shfl_down_sync(0xFFFFFFFFu, r, o);
            }
            if (lane == 0) {
                out[0] = r / (float)NTILE;                        // l_cm
                out[1] = p / (float)((size_t)NTILE * S2 * L2);    // l_c
                g_ticket = 0;                                     // rearm
                g_sync1  = 0;
            }
        }
    }
}

// ---------------------------------------------------------------------------
// Launch.  Inputs: [0] P f32, [1] index_r i32, [2] sw_abs i32, [3] lw_abs i32.
// ---------------------------------------------------------------------------
extern "C" void kernel_launch(void* const* d_in, const int* in_sizes, int n_in,
                              void* d_out, int out_size) {
    const float4* P4     = (const float4*)d_in[0];
    const float*  Pf     = (const float*)d_in[0];
    const int*    idxr   = (const int*)d_in[1];
    const int*    lw_abs = (const int*)d_in[3];
    float*        out    = (float*)d_out;

    k_all<<<NBLK, 256>>>(P4, Pf, idxr, lw_abs, out);
}